// round 8
// baseline (speedup 1.0000x reference)
#include <cuda_runtime.h>
#include <math.h>

#define NN 50000
#define EEMAX 800000
#define HH 4
#define CC 64
#define DIN 32
#define DOUT 128
#define HC 256
#define NEG_SLOPE 0.2f

// ---------------- scratch (device globals; no allocs) ----------------
__device__ __align__(16) float g_xl[NN * HC];   // 51.2 MB
__device__ __align__(16) float g_xr[NN * HC];   // 51.2 MB
__device__ __align__(16) float g_h[NN * CC];    // ELU(head-mean(GAT))
__device__ __align__(16) float g_agg[NN * CC];  // GCN-aggregated h
__device__ float g_dinv[NN];
__device__ int   g_cnt[NN];
__device__ int   g_rowptr[NN + 1];
__device__ int   g_cursor[NN];
__device__ int   g_srcidx[EEMAX];
__device__ int   g_tilesum[64];
__device__ int   g_tileoff[64];

// ================= CSR build (by dst) =================
__global__ void k_zero() {
    int i = blockIdx.x * blockDim.x + threadIdx.x;
    if (i < NN) g_cnt[i] = 0;
}

// edge_index is int32 (JAX x64 disabled: jnp.int64 request silently -> int32)
__global__ void k_hist(const int* __restrict__ ei, int E) {
    int e = blockIdx.x * blockDim.x + threadIdx.x;
    if (e < E) atomicAdd(&g_cnt[ei[E + e]], 1);
}

// tile = 1024 elems, 256 threads x 4; inclusive scan per tile -> g_rowptr[i+1]
__global__ void k_scan_tiles() {
    __shared__ int ssum[256];
    int t = threadIdx.x;
    int base = blockIdx.x * 1024 + t * 4;
    int v0 = 0, v1 = 0, v2 = 0, v3 = 0;
    if (base + 0 < NN) v0 = g_cnt[base + 0];
    if (base + 1 < NN) v1 = g_cnt[base + 1];
    if (base + 2 < NN) v2 = g_cnt[base + 2];
    if (base + 3 < NN) v3 = g_cnt[base + 3];
    v1 += v0; v2 += v1; v3 += v2;
    ssum[t] = v3;
    __syncthreads();
    for (int off = 1; off < 256; off <<= 1) {
        int a = (t >= off) ? ssum[t - off] : 0;
        __syncthreads();
        ssum[t] += a;
        __syncthreads();
    }
    int prev = (t > 0) ? ssum[t - 1] : 0;
    if (base + 0 < NN) g_rowptr[base + 1] = v0 + prev;
    if (base + 1 < NN) g_rowptr[base + 2] = v1 + prev;
    if (base + 2 < NN) g_rowptr[base + 3] = v2 + prev;
    if (base + 3 < NN) g_rowptr[base + 4] = v3 + prev;
    if (t == 255) g_tilesum[blockIdx.x] = ssum[255];
}

__global__ void k_scan_top(int ntiles) {
    __shared__ int s[64];
    int t = threadIdx.x;  // 64 threads; ntiles = 49 <= 64
    s[t] = (t < ntiles) ? g_tilesum[t] : 0;
    __syncthreads();
    for (int off = 1; off < 64; off <<= 1) {
        int a = (t >= off) ? s[t - off] : 0;
        __syncthreads();
        s[t] += a;
        __syncthreads();
    }
    g_tileoff[t] = (t > 0) ? s[t - 1] : 0;
}

__global__ void k_scan_add() {
    int i = blockIdx.x * blockDim.x + threadIdx.x;
    if (i >= NN) return;
    int incl = g_rowptr[i + 1] + g_tileoff[i >> 10];
    g_rowptr[i + 1] = incl;
    g_cursor[i] = incl - g_cnt[i];   // = rowptr[i]
    if (i == 0) g_rowptr[0] = 0;
}

__global__ void k_fill(const int* __restrict__ ei, int E) {
    int e = blockIdx.x * blockDim.x + threadIdx.x;
    if (e >= E) return;
    int src = ei[e];
    int dst = ei[E + e];
    int pos = atomicAdd(&g_cursor[dst], 1);
    g_srcidx[pos] = src;
}

// ================= xl / xr projections =================
// block = 256 threads, 16 nodes/block; W^T staged in padded smem.
#define NPB 16
__global__ __launch_bounds__(256) void k_lr(const float* __restrict__ x,
                                            const float* __restrict__ Wl,
                                            const float* __restrict__ Wr) {
    __shared__ float sW[DIN * 257];      // transposed, padded: sW[k*257 + col]
    __shared__ float sx[NPB * DIN];      // 16 node rows
    int t = threadIdx.x;
    int nb = blockIdx.x * NPB;

    for (int i = t; i < NPB * DIN; i += 256) {
        int n = i >> 5, k = i & 31;
        int node = nb + n;
        sx[i] = (node < NN) ? x[node * DIN + k] : 0.0f;
    }
    // ---- phase L ----
    for (int i = t; i < HC * DIN; i += 256) {
        int col = i >> 5, k = i & 31;
        sW[k * 257 + col] = Wl[i];
    }
    __syncthreads();
    {
        float acc[NPB];
#pragma unroll
        for (int n = 0; n < NPB; n++) acc[n] = 0.0f;
#pragma unroll
        for (int k = 0; k < DIN; k++) {
            float w = sW[k * 257 + t];
#pragma unroll
            for (int n = 0; n < NPB; n++) acc[n] = fmaf(w, sx[n * DIN + k], acc[n]);
        }
#pragma unroll
        for (int n = 0; n < NPB; n++) {
            int node = nb + n;
            if (node < NN) g_xl[(size_t)node * HC + t] = acc[n];
        }
    }
    __syncthreads();
    // ---- phase R ----
    for (int i = t; i < HC * DIN; i += 256) {
        int col = i >> 5, k = i & 31;
        sW[k * 257 + col] = Wr[i];
    }
    __syncthreads();
    {
        float acc[NPB];
#pragma unroll
        for (int n = 0; n < NPB; n++) acc[n] = 0.0f;
#pragma unroll
        for (int k = 0; k < DIN; k++) {
            float w = sW[k * 257 + t];
#pragma unroll
            for (int n = 0; n < NPB; n++) acc[n] = fmaf(w, sx[n * DIN + k], acc[n]);
        }
#pragma unroll
        for (int n = 0; n < NPB; n++) {
            int node = nb + n;
            if (node < NN) g_xr[(size_t)node * HC + t] = acc[n];
        }
    }
}

// ================= fused GAT (warp per node, dual-state online softmax) ======
// lane serves channels [lane*8, lane*8+8); head = lane>>3.
struct SMState {
    float m, s;
    float acc[8];
};

__device__ __forceinline__ void sm_init(SMState& st) {
    st.m = -INFINITY; st.s = 0.0f;
#pragma unroll
    for (int j = 0; j < 8; j++) st.acc[j] = 0.0f;
}

__device__ __forceinline__ void sm_update(SMState& st, float l,
                                          const float4& a, const float4& b) {
    float mn = fmaxf(st.m, l);
    float scale = __expf(st.m - mn);
    float p = __expf(l - mn);
    st.s = st.s * scale + p;
    st.m = mn;
    st.acc[0] = st.acc[0] * scale + p * a.x;
    st.acc[1] = st.acc[1] * scale + p * a.y;
    st.acc[2] = st.acc[2] * scale + p * a.z;
    st.acc[3] = st.acc[3] * scale + p * a.w;
    st.acc[4] = st.acc[4] * scale + p * b.x;
    st.acc[5] = st.acc[5] * scale + p * b.y;
    st.acc[6] = st.acc[6] * scale + p * b.z;
    st.acc[7] = st.acc[7] * scale + p * b.w;
}

__device__ __forceinline__ float edge_logit(const float4& a, const float4& b,
                                            const float4& xr0, const float4& xr1,
                                            const float4& at0, const float4& at1) {
    float p0 = a.x + xr0.x; p0 = (p0 > 0.f) ? p0 : NEG_SLOPE * p0;
    float p1 = a.y + xr0.y; p1 = (p1 > 0.f) ? p1 : NEG_SLOPE * p1;
    float p2 = a.z + xr0.z; p2 = (p2 > 0.f) ? p2 : NEG_SLOPE * p2;
    float p3 = a.w + xr0.w; p3 = (p3 > 0.f) ? p3 : NEG_SLOPE * p3;
    float p4 = b.x + xr1.x; p4 = (p4 > 0.f) ? p4 : NEG_SLOPE * p4;
    float p5 = b.y + xr1.y; p5 = (p5 > 0.f) ? p5 : NEG_SLOPE * p5;
    float p6 = b.z + xr1.z; p6 = (p6 > 0.f) ? p6 : NEG_SLOPE * p6;
    float p7 = b.w + xr1.w; p7 = (p7 > 0.f) ? p7 : NEG_SLOPE * p7;
    float part = p0 * at0.x + p1 * at0.y + p2 * at0.z + p3 * at0.w
               + p4 * at1.x + p5 * at1.y + p6 * at1.z + p7 * at1.w;
    part += __shfl_xor_sync(0xffffffffu, part, 1);
    part += __shfl_xor_sync(0xffffffffu, part, 2);
    part += __shfl_xor_sync(0xffffffffu, part, 4);
    return part;
}

__global__ __launch_bounds__(256) void k_gat(const float* __restrict__ att) {
    int w = (blockIdx.x * blockDim.x + threadIdx.x) >> 5;
    int lane = threadIdx.x & 31;
    if (w >= NN) return;
    int node = w;
    int beg = g_rowptr[node], end = g_rowptr[node + 1];

    const float4* ap = (const float4*)(att + lane * 8);
    float4 at0 = ap[0], at1 = ap[1];
    const float4* xrp = (const float4*)(g_xr + (size_t)node * HC + lane * 8);
    float4 xr0 = xrp[0], xr1 = xrp[1];

    SMState A, B;
    sm_init(A); sm_init(B);

    int e = beg;
    // dual-issue: 2 edges per iteration, independent states -> MLP ~4-5
    for (; e + 1 < end; e += 2) {
        int s0 = __ldg(g_srcidx + e);
        int s1 = __ldg(g_srcidx + e + 1);
        const float4* x0 = (const float4*)(g_xl + (size_t)s0 * HC + lane * 8);
        const float4* x1 = (const float4*)(g_xl + (size_t)s1 * HC + lane * 8);
        float4 a0 = x0[0], b0 = x0[1];
        float4 a1 = x1[0], b1 = x1[1];

        float l0 = edge_logit(a0, b0, xr0, xr1, at0, at1);
        float l1 = edge_logit(a1, b1, xr0, xr1, at0, at1);
        sm_update(A, l0, a0, b0);
        sm_update(B, l1, a1, b1);
    }
    if (e < end) {
        int s0 = __ldg(g_srcidx + e);
        const float4* x0 = (const float4*)(g_xl + (size_t)s0 * HC + lane * 8);
        float4 a0 = x0[0], b0 = x0[1];
        float l0 = edge_logit(a0, b0, xr0, xr1, at0, at1);
        sm_update(A, l0, a0, b0);
    }

    // merge B into A (guard the both-empty NaN case)
    float res[8];
    float mn = fmaxf(A.m, B.m);
    if (mn == -INFINITY) {
#pragma unroll
        for (int j = 0; j < 8; j++) res[j] = 0.0f;
    } else {
        float scA = (A.m == -INFINITY) ? 0.0f : __expf(A.m - mn);
        float scB = (B.m == -INFINITY) ? 0.0f : __expf(B.m - mn);
        float s = A.s * scA + B.s * scB;
        float inv = (s > 0.0f) ? 1.0f / s : 0.0f;
#pragma unroll
        for (int j = 0; j < 8; j++)
            res[j] = (A.acc[j] * scA + B.acc[j] * scB) * inv;
    }

#pragma unroll
    for (int j = 0; j < 8; j++) {
        float v = res[j];
        // head mean: lanes L, L^8, L^16, L^24 hold the same per-head channel
        v += __shfl_xor_sync(0xffffffffu, v, 8);
        v += __shfl_xor_sync(0xffffffffu, v, 16);
        res[j] = v;
    }
    if (lane < 8) {
        float* hp = g_h + (size_t)node * CC + lane * 8;
#pragma unroll
        for (int j = 0; j < 8; j++) {
            float v = 0.25f * res[j];
            hp[j] = (v > 0.0f) ? v : (__expf(v) - 1.0f);  // ELU
        }
    }
    if (lane == 0) {
        int d = end - beg;
        g_dinv[node] = (d > 0) ? rsqrtf((float)d) : 0.0f;
    }
}

// ================= GCN aggregate (warp per node, gather-side, 64-dim) ========
__global__ __launch_bounds__(256) void k_gcn(void) {
    int w = (blockIdx.x * blockDim.x + threadIdx.x) >> 5;
    int lane = threadIdx.x & 31;
    if (w >= NN) return;
    int beg = g_rowptr[w], end = g_rowptr[w + 1];
    float di = g_dinv[w];
    float a0 = 0.f, a1 = 0.f, a2 = 0.f, a3 = 0.f;
    int e = beg;
    for (; e + 1 < end; e += 2) {
        int s0 = __ldg(g_srcidx + e);
        int s1 = __ldg(g_srcidx + e + 1);
        float n0 = di * __ldg(g_dinv + s0);
        float n1 = di * __ldg(g_dinv + s1);
        float2 v0 = *(const float2*)(g_h + (size_t)s0 * CC + lane * 2);
        float2 v1 = *(const float2*)(g_h + (size_t)s1 * CC + lane * 2);
        a0 = fmaf(n0, v0.x, a0);
        a1 = fmaf(n0, v0.y, a1);
        a2 = fmaf(n1, v1.x, a2);
        a3 = fmaf(n1, v1.y, a3);
    }
    if (e < end) {
        int s0 = __ldg(g_srcidx + e);
        float n0 = di * __ldg(g_dinv + s0);
        float2 v0 = *(const float2*)(g_h + (size_t)s0 * CC + lane * 2);
        a0 = fmaf(n0, v0.x, a0);
        a1 = fmaf(n0, v0.y, a1);
    }
    float2 r; r.x = a0 + a2; r.y = a1 + a3;
    *(float2*)(g_agg + (size_t)w * CC + lane * 2) = r;
}

// ================= decoder GEMM: out = agg @ Wg^T =================
// block = 128 threads (one output col each), 64 nodes per block, 2 per iter.
__global__ __launch_bounds__(128) void k_dec(const float* __restrict__ Wg,
                                             float* __restrict__ out) {
    __shared__ float sW[CC * 129];   // transposed, padded: sW[c*129 + row]
    __shared__ float sh[2 * CC];
    int t = threadIdx.x;
    for (int i = t; i < DOUT * CC; i += 128) {
        int row = i >> 6, c = i & 63;
        sW[c * 129 + row] = Wg[i];
    }
    int nb = blockIdx.x * 64;
    for (int kk = 0; kk < 64; kk += 2) {
        int node0 = nb + kk;
        __syncthreads();
        {   // stage 2 node rows
            int which = t >> 6, c = t & 63;
            int node = node0 + which;
            sh[t] = (node < NN) ? g_agg[(size_t)node * CC + c] : 0.0f;
        }
        __syncthreads();
#pragma unroll
        for (int q = 0; q < 2; q++) {
            int node = node0 + q;
            if (node < NN) {
                float a = 0.0f;
#pragma unroll
                for (int c = 0; c < CC; c++) a = fmaf(sW[c * 129 + t], sh[q * CC + c], a);
                out[(size_t)node * DOUT + t] = a;
            }
        }
    }
}

// ================= launch =================
extern "C" void kernel_launch(void* const* d_in, const int* in_sizes, int n_in,
                              void* d_out, int out_size) {
    const float* x   = (const float*)d_in[0];
    const int*   ei  = (const int*)d_in[1];    // int32 edge_index (JAX x64 off)
    const float* Wl  = (const float*)d_in[2];
    const float* Wr  = (const float*)d_in[3];
    const float* att = (const float*)d_in[4];
    const float* Wg  = (const float*)d_in[5];
    float* out       = (float*)d_out;

    const int E = in_sizes[1] / 2;
    const int eb = (E + 255) / 256;
    const int ntiles = (NN + 1023) / 1024;      // 49
    const int nwb = (NN * 32 + 255) / 256;      // warp-per-node grids

    k_zero<<<(NN + 255) / 256, 256>>>();
    k_hist<<<eb, 256>>>(ei, E);
    k_scan_tiles<<<ntiles, 256>>>();
    k_scan_top<<<1, 64>>>(ntiles);
    k_scan_add<<<(NN + 255) / 256, 256>>>();
    k_fill<<<eb, 256>>>(ei, E);

    k_lr<<<(NN + NPB - 1) / NPB, 256>>>(x, Wl, Wr);
    k_gat<<<nwb, 256>>>(att);
    k_gcn<<<nwb, 256>>>();
    k_dec<<<(NN + 63) / 64, 128>>>(Wg, out);
}

// round 10
// speedup vs baseline: 1.2260x; 1.2260x over previous
#include <cuda_runtime.h>
#include <math.h>

#define NN 50000
#define EEMAX 800000
#define HH 4
#define CC 64
#define DIN 32
#define DOUT 128
#define HC 256
#define NEG_SLOPE 0.2f

// ---------------- scratch (device globals; no allocs) ----------------
__device__ __align__(16) float g_xl[NN * HC];   // 51.2 MB
__device__ __align__(16) float g_xr[NN * HC];   // 51.2 MB
__device__ __align__(16) float g_h[NN * CC];    // ELU(head-mean(GAT))
__device__ __align__(16) float g_agg[NN * CC];  // GCN-aggregated h
__device__ float g_dinv[NN];
__device__ int   g_cnt[NN];
__device__ int   g_rowptr[NN + 1];
__device__ int   g_cursor[NN];
__device__ int   g_srcidx[EEMAX];
__device__ int   g_tilesum[64];
__device__ int   g_tileoff[64];

// ================= CSR build (by dst) =================
__global__ void k_zero() {
    int i = blockIdx.x * blockDim.x + threadIdx.x;
    if (i < NN) g_cnt[i] = 0;
}

// edge_index is int32 (JAX x64 disabled: jnp.int64 request silently -> int32)
__global__ void k_hist(const int* __restrict__ ei, int E) {
    int e = blockIdx.x * blockDim.x + threadIdx.x;
    if (e < E) atomicAdd(&g_cnt[ei[E + e]], 1);
}

// tile = 1024 elems, 256 threads x 4; inclusive scan per tile -> g_rowptr[i+1]
__global__ void k_scan_tiles() {
    __shared__ int ssum[256];
    int t = threadIdx.x;
    int base = blockIdx.x * 1024 + t * 4;
    int v0 = 0, v1 = 0, v2 = 0, v3 = 0;
    if (base + 0 < NN) v0 = g_cnt[base + 0];
    if (base + 1 < NN) v1 = g_cnt[base + 1];
    if (base + 2 < NN) v2 = g_cnt[base + 2];
    if (base + 3 < NN) v3 = g_cnt[base + 3];
    v1 += v0; v2 += v1; v3 += v2;
    ssum[t] = v3;
    __syncthreads();
    for (int off = 1; off < 256; off <<= 1) {
        int a = (t >= off) ? ssum[t - off] : 0;
        __syncthreads();
        ssum[t] += a;
        __syncthreads();
    }
    int prev = (t > 0) ? ssum[t - 1] : 0;
    if (base + 0 < NN) g_rowptr[base + 1] = v0 + prev;
    if (base + 1 < NN) g_rowptr[base + 2] = v1 + prev;
    if (base + 2 < NN) g_rowptr[base + 3] = v2 + prev;
    if (base + 3 < NN) g_rowptr[base + 4] = v3 + prev;
    if (t == 255) g_tilesum[blockIdx.x] = ssum[255];
}

__global__ void k_scan_top(int ntiles) {
    __shared__ int s[64];
    int t = threadIdx.x;  // 64 threads; ntiles = 49 <= 64
    s[t] = (t < ntiles) ? g_tilesum[t] : 0;
    __syncthreads();
    for (int off = 1; off < 64; off <<= 1) {
        int a = (t >= off) ? s[t - off] : 0;
        __syncthreads();
        s[t] += a;
        __syncthreads();
    }
    g_tileoff[t] = (t > 0) ? s[t - 1] : 0;
}

__global__ void k_scan_add() {
    int i = blockIdx.x * blockDim.x + threadIdx.x;
    if (i >= NN) return;
    int incl = g_rowptr[i + 1] + g_tileoff[i >> 10];
    g_rowptr[i + 1] = incl;
    g_cursor[i] = incl - g_cnt[i];   // = rowptr[i]
    if (i == 0) g_rowptr[0] = 0;
}

__global__ void k_fill(const int* __restrict__ ei, int E) {
    int e = blockIdx.x * blockDim.x + threadIdx.x;
    if (e >= E) return;
    int src = ei[e];
    int dst = ei[E + e];
    int pos = atomicAdd(&g_cursor[dst], 1);
    g_srcidx[pos] = src;
}

// ================= xl / xr projections =================
// block = 256 threads (t = output column), 32 nodes/block.
// Weights held in REGISTERS (staged once via conflict-free smem);
// x rows broadcast from smem via LDS.128 -> LDS:FFMA = 1:4.
#define NPB 32
__global__ __launch_bounds__(256) void k_lr(const float* __restrict__ x,
                                            const float* __restrict__ Wl,
                                            const float* __restrict__ Wr) {
    __shared__ __align__(16) float sW[DIN * 257];   // sW[k*257 + col]
    __shared__ __align__(16) float sx[NPB * DIN];   // 32 node rows (4 KB)
    int t = threadIdx.x;
    int nb = blockIdx.x * NPB;

    // stage x rows (coalesced)
    for (int i = t; i < NPB * DIN; i += 256) {
        int n = i >> 5, k = i & 31;
        int node = nb + n;
        sx[i] = (node < NN) ? x[node * DIN + k] : 0.0f;
    }

    float w[DIN];

    // ---- phase L ----
    for (int i = t; i < HC * DIN; i += 256) {
        int col = i >> 5, k = i & 31;
        sW[k * 257 + col] = Wl[i];
    }
    __syncthreads();
#pragma unroll
    for (int k = 0; k < DIN; k++) w[k] = sW[k * 257 + t];  // conflict-free

    for (int n = 0; n < NPB; n++) {
        const float4* xv = (const float4*)(sx + n * DIN);
        float a0 = 0.f, a1 = 0.f, a2 = 0.f, a3 = 0.f;
#pragma unroll
        for (int j = 0; j < 8; j++) {
            float4 xx = xv[j];                 // LDS.128 broadcast
            a0 = fmaf(w[4 * j + 0], xx.x, a0);
            a1 = fmaf(w[4 * j + 1], xx.y, a1);
            a2 = fmaf(w[4 * j + 2], xx.z, a2);
            a3 = fmaf(w[4 * j + 3], xx.w, a3);
        }
        int node = nb + n;
        if (node < NN) g_xl[(size_t)node * HC + t] = (a0 + a1) + (a2 + a3);
    }
    __syncthreads();

    // ---- phase R ----
    for (int i = t; i < HC * DIN; i += 256) {
        int col = i >> 5, k = i & 31;
        sW[k * 257 + col] = Wr[i];
    }
    __syncthreads();
#pragma unroll
    for (int k = 0; k < DIN; k++) w[k] = sW[k * 257 + t];

    for (int n = 0; n < NPB; n++) {
        const float4* xv = (const float4*)(sx + n * DIN);
        float a0 = 0.f, a1 = 0.f, a2 = 0.f, a3 = 0.f;
#pragma unroll
        for (int j = 0; j < 8; j++) {
            float4 xx = xv[j];
            a0 = fmaf(w[4 * j + 0], xx.x, a0);
            a1 = fmaf(w[4 * j + 1], xx.y, a1);
            a2 = fmaf(w[4 * j + 2], xx.z, a2);
            a3 = fmaf(w[4 * j + 3], xx.w, a3);
        }
        int node = nb + n;
        if (node < NN) g_xr[(size_t)node * HC + t] = (a0 + a1) + (a2 + a3);
    }
}

// ================= fused GAT (warp per node, dual-state online softmax) ======
// lane serves channels [lane*8, lane*8+8); head = lane>>3.
struct SMState {
    float m, s;
    float acc[8];
};

__device__ __forceinline__ void sm_init(SMState& st) {
    st.m = -INFINITY; st.s = 0.0f;
#pragma unroll
    for (int j = 0; j < 8; j++) st.acc[j] = 0.0f;
}

__device__ __forceinline__ void sm_update(SMState& st, float l,
                                          const float4& a, const float4& b) {
    float mn = fmaxf(st.m, l);
    float scale = __expf(st.m - mn);
    float p = __expf(l - mn);
    st.s = st.s * scale + p;
    st.m = mn;
    st.acc[0] = st.acc[0] * scale + p * a.x;
    st.acc[1] = st.acc[1] * scale + p * a.y;
    st.acc[2] = st.acc[2] * scale + p * a.z;
    st.acc[3] = st.acc[3] * scale + p * a.w;
    st.acc[4] = st.acc[4] * scale + p * b.x;
    st.acc[5] = st.acc[5] * scale + p * b.y;
    st.acc[6] = st.acc[6] * scale + p * b.z;
    st.acc[7] = st.acc[7] * scale + p * b.w;
}

__device__ __forceinline__ float edge_logit(const float4& a, const float4& b,
                                            const float4& xr0, const float4& xr1,
                                            const float4& at0, const float4& at1) {
    float p0 = a.x + xr0.x; p0 = (p0 > 0.f) ? p0 : NEG_SLOPE * p0;
    float p1 = a.y + xr0.y; p1 = (p1 > 0.f) ? p1 : NEG_SLOPE * p1;
    float p2 = a.z + xr0.z; p2 = (p2 > 0.f) ? p2 : NEG_SLOPE * p2;
    float p3 = a.w + xr0.w; p3 = (p3 > 0.f) ? p3 : NEG_SLOPE * p3;
    float p4 = b.x + xr1.x; p4 = (p4 > 0.f) ? p4 : NEG_SLOPE * p4;
    float p5 = b.y + xr1.y; p5 = (p5 > 0.f) ? p5 : NEG_SLOPE * p5;
    float p6 = b.z + xr1.z; p6 = (p6 > 0.f) ? p6 : NEG_SLOPE * p6;
    float p7 = b.w + xr1.w; p7 = (p7 > 0.f) ? p7 : NEG_SLOPE * p7;
    float part = p0 * at0.x + p1 * at0.y + p2 * at0.z + p3 * at0.w
               + p4 * at1.x + p5 * at1.y + p6 * at1.z + p7 * at1.w;
    part += __shfl_xor_sync(0xffffffffu, part, 1);
    part += __shfl_xor_sync(0xffffffffu, part, 2);
    part += __shfl_xor_sync(0xffffffffu, part, 4);
    return part;
}

__global__ __launch_bounds__(256) void k_gat(const float* __restrict__ att) {
    int w = (blockIdx.x * blockDim.x + threadIdx.x) >> 5;
    int lane = threadIdx.x & 31;
    if (w >= NN) return;
    int node = w;
    int beg = g_rowptr[node], end = g_rowptr[node + 1];

    const float4* ap = (const float4*)(att + lane * 8);
    float4 at0 = ap[0], at1 = ap[1];
    const float4* xrp = (const float4*)(g_xr + (size_t)node * HC + lane * 8);
    float4 xr0 = xrp[0], xr1 = xrp[1];

    SMState A, B;
    sm_init(A); sm_init(B);

    int e = beg;
    for (; e + 1 < end; e += 2) {
        int s0 = __ldg(g_srcidx + e);
        int s1 = __ldg(g_srcidx + e + 1);
        const float4* x0 = (const float4*)(g_xl + (size_t)s0 * HC + lane * 8);
        const float4* x1 = (const float4*)(g_xl + (size_t)s1 * HC + lane * 8);
        float4 a0 = x0[0], b0 = x0[1];
        float4 a1 = x1[0], b1 = x1[1];

        float l0 = edge_logit(a0, b0, xr0, xr1, at0, at1);
        float l1 = edge_logit(a1, b1, xr0, xr1, at0, at1);
        sm_update(A, l0, a0, b0);
        sm_update(B, l1, a1, b1);
    }
    if (e < end) {
        int s0 = __ldg(g_srcidx + e);
        const float4* x0 = (const float4*)(g_xl + (size_t)s0 * HC + lane * 8);
        float4 a0 = x0[0], b0 = x0[1];
        float l0 = edge_logit(a0, b0, xr0, xr1, at0, at1);
        sm_update(A, l0, a0, b0);
    }

    // merge B into A (guard the both-empty NaN case)
    float res[8];
    float mn = fmaxf(A.m, B.m);
    if (mn == -INFINITY) {
#pragma unroll
        for (int j = 0; j < 8; j++) res[j] = 0.0f;
    } else {
        float scA = (A.m == -INFINITY) ? 0.0f : __expf(A.m - mn);
        float scB = (B.m == -INFINITY) ? 0.0f : __expf(B.m - mn);
        float s = A.s * scA + B.s * scB;
        float inv = (s > 0.0f) ? 1.0f / s : 0.0f;
#pragma unroll
        for (int j = 0; j < 8; j++)
            res[j] = (A.acc[j] * scA + B.acc[j] * scB) * inv;
    }

#pragma unroll
    for (int j = 0; j < 8; j++) {
        float v = res[j];
        // head mean: lanes L, L^8, L^16, L^24 hold the same per-head channel
        v += __shfl_xor_sync(0xffffffffu, v, 8);
        v += __shfl_xor_sync(0xffffffffu, v, 16);
        res[j] = v;
    }
    if (lane < 8) {
        float* hp = g_h + (size_t)node * CC + lane * 8;
#pragma unroll
        for (int j = 0; j < 8; j++) {
            float v = 0.25f * res[j];
            hp[j] = (v > 0.0f) ? v : (__expf(v) - 1.0f);  // ELU
        }
    }
    if (lane == 0) {
        int d = end - beg;
        g_dinv[node] = (d > 0) ? rsqrtf((float)d) : 0.0f;
    }
}

// ================= GCN aggregate (warp per node, gather-side, 64-dim) ========
__global__ __launch_bounds__(256) void k_gcn(void) {
    int w = (blockIdx.x * blockDim.x + threadIdx.x) >> 5;
    int lane = threadIdx.x & 31;
    if (w >= NN) return;
    int beg = g_rowptr[w], end = g_rowptr[w + 1];
    float di = g_dinv[w];
    float a0 = 0.f, a1 = 0.f, a2 = 0.f, a3 = 0.f;
    int e = beg;
    for (; e + 1 < end; e += 2) {
        int s0 = __ldg(g_srcidx + e);
        int s1 = __ldg(g_srcidx + e + 1);
        float n0 = di * __ldg(g_dinv + s0);
        float n1 = di * __ldg(g_dinv + s1);
        float2 v0 = *(const float2*)(g_h + (size_t)s0 * CC + lane * 2);
        float2 v1 = *(const float2*)(g_h + (size_t)s1 * CC + lane * 2);
        a0 = fmaf(n0, v0.x, a0);
        a1 = fmaf(n0, v0.y, a1);
        a2 = fmaf(n1, v1.x, a2);
        a3 = fmaf(n1, v1.y, a3);
    }
    if (e < end) {
        int s0 = __ldg(g_srcidx + e);
        float n0 = di * __ldg(g_dinv + s0);
        float2 v0 = *(const float2*)(g_h + (size_t)s0 * CC + lane * 2);
        a0 = fmaf(n0, v0.x, a0);
        a1 = fmaf(n0, v0.y, a1);
    }
    float2 r; r.x = a0 + a2; r.y = a1 + a3;
    *(float2*)(g_agg + (size_t)w * CC + lane * 2) = r;
}

// ================= decoder GEMM: out = agg @ Wg^T =================
// block = 128 threads (t = output col), 64 nodes/block.
// Wg row held in REGISTERS; agg row broadcast via LDS.128 -> LDS:FFMA = 1:4.
__global__ __launch_bounds__(128) void k_dec(const float* __restrict__ Wg,
                                             float* __restrict__ out) {
    __shared__ __align__(16) float sW[DOUT * 65];  // sW[row*65 + c]
    __shared__ __align__(16) float sh[2 * CC];
    int t = threadIdx.x;
    for (int i = t; i < DOUT * CC; i += 128) {
        int row = i >> 6, c = i & 63;
        sW[row * 65 + c] = Wg[i];        // coalesced-ish staging
    }
    __syncthreads();
    float w[CC];
#pragma unroll
    for (int c = 0; c < CC; c++) w[c] = sW[t * 65 + c];  // stride-65: conflict-free

    int nb = blockIdx.x * 64;
    for (int kk = 0; kk < 64; kk += 2) {
        int node0 = nb + kk;
        __syncthreads();
        {   // stage 2 node rows
            int which = t >> 6, c = t & 63;
            int node = node0 + which;
            sh[t] = (node < NN) ? g_agg[(size_t)node * CC + c] : 0.0f;
        }
        __syncthreads();
#pragma unroll
        for (int q = 0; q < 2; q++) {
            int node = node0 + q;
            if (node < NN) {
                const float4* hv = (const float4*)(sh + q * CC);
                float a0 = 0.f, a1 = 0.f, a2 = 0.f, a3 = 0.f;
#pragma unroll
                for (int j = 0; j < 16; j++) {
                    float4 hh = hv[j];               // LDS.128 broadcast
                    a0 = fmaf(w[4 * j + 0], hh.x, a0);
                    a1 = fmaf(w[4 * j + 1], hh.y, a1);
                    a2 = fmaf(w[4 * j + 2], hh.z, a2);
                    a3 = fmaf(w[4 * j + 3], hh.w, a3);
                }
                out[(size_t)node * DOUT + t] = (a0 + a1) + (a2 + a3);
            }
        }
    }
}

// ================= launch =================
extern "C" void kernel_launch(void* const* d_in, const int* in_sizes, int n_in,
                              void* d_out, int out_size) {
    const float* x   = (const float*)d_in[0];
    const int*   ei  = (const int*)d_in[1];    // int32 edge_index (JAX x64 off)
    const float* Wl  = (const float*)d_in[2];
    const float* Wr  = (const float*)d_in[3];
    const float* att = (const float*)d_in[4];
    const float* Wg  = (const float*)d_in[5];
    float* out       = (float*)d_out;

    const int E = in_sizes[1] / 2;
    const int eb = (E + 255) / 256;
    const int ntiles = (NN + 1023) / 1024;      // 49
    const int nwb = (NN * 32 + 255) / 256;      // warp-per-node grids

    k_zero<<<(NN + 255) / 256, 256>>>();
    k_hist<<<eb, 256>>>(ei, E);
    k_scan_tiles<<<ntiles, 256>>>();
    k_scan_top<<<1, 64>>>(ntiles);
    k_scan_add<<<(NN + 255) / 256, 256>>>();
    k_fill<<<eb, 256>>>(ei, E);

    k_lr<<<(NN + NPB - 1) / NPB, 256>>>(x, Wl, Wr);
    k_gat<<<nwb, 256>>>(att);
    k_gcn<<<nwb, 256>>>();
    k_dec<<<(NN + 63) / 64, 128>>>(Wg, out);
}